// round 5
// baseline (speedup 1.0000x reference)
#include <cuda_runtime.h>
#include <cuda_bf16.h>
#include <cstdint>
#include <cstddef>

// FFN: out = relu(x @ w1 + b1) @ w2 + b2
// bf16x3 split precision via mma.sync.m16n8k16; term-major MMA order, 1 sync/iter.

#define M_TOTAL 8192
#define D_DIM   1024
#define W_DIM   4096

// ---- device scratch ----
__device__ __nv_bfloat16 g_xh[(size_t)M_TOTAL * D_DIM];
__device__ __nv_bfloat16 g_xl[(size_t)M_TOTAL * D_DIM];
__device__ __nv_bfloat16 g_hh[(size_t)M_TOTAL * W_DIM];
__device__ __nv_bfloat16 g_hl[(size_t)M_TOTAL * W_DIM];
__device__ __nv_bfloat16 g_w1th[(size_t)W_DIM * D_DIM];
__device__ __nv_bfloat16 g_w1tl[(size_t)W_DIM * D_DIM];
__device__ __nv_bfloat16 g_w2th[(size_t)D_DIM * W_DIM];
__device__ __nv_bfloat16 g_w2tl[(size_t)D_DIM * W_DIM];

// ---- helpers ----
__device__ __forceinline__ uint32_t smem_u32(const void* p) {
    uint32_t a;
    asm("{ .reg .u64 t; cvta.to.shared.u64 t, %1; cvt.u32.u64 %0, t; }" : "=r"(a) : "l"(p));
    return a;
}
__device__ __forceinline__ void cpasync16(uint32_t dst, const void* src) {
    asm volatile("cp.async.cg.shared.global [%0], [%1], 16;" :: "r"(dst), "l"(src));
}
__device__ __forceinline__ void cp_commit() {
    asm volatile("cp.async.commit_group;" ::: "memory");
}
__device__ __forceinline__ void cp_wait1() {
    asm volatile("cp.async.wait_group 1;" ::: "memory");
}
__device__ __forceinline__ void ldsm4(uint32_t* r, uint32_t addr) {
    asm volatile("ldmatrix.sync.aligned.m8n8.x4.shared.b16 {%0,%1,%2,%3}, [%4];"
                 : "=r"(r[0]), "=r"(r[1]), "=r"(r[2]), "=r"(r[3]) : "r"(addr));
}
__device__ __forceinline__ void mma16816(float* c, const uint32_t* a, uint32_t b0, uint32_t b1) {
    asm volatile("mma.sync.aligned.m16n8k16.row.col.f32.bf16.bf16.f32 "
                 "{%0,%1,%2,%3}, {%4,%5,%6,%7}, {%8,%9}, {%0,%1,%2,%3};"
                 : "+f"(c[0]), "+f"(c[1]), "+f"(c[2]), "+f"(c[3])
                 : "r"(a[0]), "r"(a[1]), "r"(a[2]), "r"(a[3]), "r"(b0), "r"(b1));
}
__device__ __forceinline__ void split_bf16(float v, __nv_bfloat16& hi, __nv_bfloat16& lo) {
    hi = __float2bfloat16_rn(v);
    lo = __float2bfloat16_rn(v - __bfloat162float(hi));
}

// ---- prepass: split fp32 -> bf16 hi/lo ----
__global__ void split_kernel(const float* __restrict__ X,
                             __nv_bfloat16* __restrict__ Xh,
                             __nv_bfloat16* __restrict__ Xl, size_t n4) {
    size_t i = (size_t)blockIdx.x * blockDim.x + threadIdx.x;
    if (i >= n4) return;
    float4 v = ((const float4*)X)[i];
    __nv_bfloat16 h0, h1, h2, h3, l0, l1, l2, l3;
    split_bf16(v.x, h0, l0); split_bf16(v.y, h1, l1);
    split_bf16(v.z, h2, l2); split_bf16(v.w, h3, l3);
    uint32_t ph0 = ((uint32_t)__bfloat16_as_ushort(h1) << 16) | __bfloat16_as_ushort(h0);
    uint32_t ph1 = ((uint32_t)__bfloat16_as_ushort(h3) << 16) | __bfloat16_as_ushort(h2);
    uint32_t pl0 = ((uint32_t)__bfloat16_as_ushort(l1) << 16) | __bfloat16_as_ushort(l0);
    uint32_t pl1 = ((uint32_t)__bfloat16_as_ushort(l3) << 16) | __bfloat16_as_ushort(l2);
    ((uint2*)Xh)[i] = make_uint2(ph0, ph1);
    ((uint2*)Xl)[i] = make_uint2(pl0, pl1);
}

// ---- prepass: W [K,N] fp32 -> W^T [N,K] bf16 hi/lo ----
__global__ void transpose_split_kernel(const float* __restrict__ W,
                                       __nv_bfloat16* __restrict__ Thi,
                                       __nv_bfloat16* __restrict__ Tlo,
                                       int K, int N) {
    __shared__ float t[32][33];
    int n0 = blockIdx.x * 32, k0 = blockIdx.y * 32;
    int tx = threadIdx.x, ty = threadIdx.y;
    #pragma unroll
    for (int j = 0; j < 4; j++)
        t[ty + 8 * j][tx] = W[(size_t)(k0 + ty + 8 * j) * N + n0 + tx];
    __syncthreads();
    #pragma unroll
    for (int j = 0; j < 4; j++) {
        float v = t[tx][ty + 8 * j];
        __nv_bfloat16 hi, lo;
        split_bf16(v, hi, lo);
        size_t o = (size_t)(n0 + ty + 8 * j) * K + k0 + tx;
        Thi[o] = hi;
        Tlo[o] = lo;
    }
}

// ---- main GEMM ----
#define BMT 128
#define BNT 128
#define BKT 32
#define STAGES 3
#define ROWB 80
#define TILE_B (128 * ROWB)
#define STAGE_B (4 * TILE_B)
#define OFF_AH 0
#define OFF_AL TILE_B
#define OFF_BH (2 * TILE_B)
#define OFF_BL (3 * TILE_B)
#define SMEM_DYN (STAGES * STAGE_B)

template<bool SPLIT_OUT>
__global__ __launch_bounds__(256, 1)
void ffn_mma(const __nv_bfloat16* __restrict__ Ah, const __nv_bfloat16* __restrict__ Al,
             const __nv_bfloat16* __restrict__ Bh, const __nv_bfloat16* __restrict__ Bl,
             const float* __restrict__ bias,
             float* __restrict__ Cf,
             __nv_bfloat16* __restrict__ Chi, __nv_bfloat16* __restrict__ Clo,
             int M, int N, int K) {
    extern __shared__ char smem[];
    const uint32_t sbase = smem_u32(smem);
    const int tid = threadIdx.x;
    const int lane = tid & 31, wid = tid >> 5;
    const int wm = (wid >> 1) * 32, wn = (wid & 1) * 64;
    const int bm = blockIdx.y * BMT, bn = blockIdx.x * BNT;

    const __nv_bfloat16* Ahb = Ah + (size_t)bm * K;
    const __nv_bfloat16* Alb = Al + (size_t)bm * K;
    const __nv_bfloat16* Bhb = Bh + (size_t)bn * K;
    const __nv_bfloat16* Blb = Bl + (size_t)bn * K;

    const int ldr = tid >> 2;
    const int ldc = tid & 3;

    const int nIters = K / BKT;

    auto issue_stage = [&](int s) {
        uint32_t dst = sbase + (uint32_t)(s % STAGES) * STAGE_B;
        int k0 = s * BKT;
        #pragma unroll
        for (int h = 0; h < 2; h++) {
            int row = ldr + h * 64;
            uint32_t d = dst + (uint32_t)row * ROWB + (uint32_t)ldc * 16;
            size_t so = (size_t)row * K + k0 + ldc * 8;
            cpasync16(d + OFF_AH, Ahb + so);
            cpasync16(d + OFF_AL, Alb + so);
            cpasync16(d + OFF_BH, Bhb + so);
            cpasync16(d + OFF_BL, Blb + so);
        }
        cp_commit();
    };

    issue_stage(0);
    issue_stage(1);

    float acc[2][8][4];
    #pragma unroll
    for (int mi = 0; mi < 2; mi++)
        #pragma unroll
        for (int f = 0; f < 8; f++)
            #pragma unroll
            for (int q = 0; q < 4; q++)
                acc[mi][f][q] = 0.0f;

    const uint32_t arow = (uint32_t)(lane & 15) * ROWB + (uint32_t)(lane >> 4) * 16;

    for (int i = 0; i < nIters; i++) {
        cp_wait1();
        __syncthreads();
        // Safe: all warps passed this barrier => all finished reading stage
        // (i-1)%3, which is exactly the buffer stage i+2 writes.
        if (i + 2 < nIters) issue_stage(i + 2);
        else cp_commit();   // keep group accounting exact for wait_group 1

        uint32_t sa = sbase + (uint32_t)(i % STAGES) * STAGE_B;

        #pragma unroll
        for (int kk = 0; kk < 2; kk++) {
            uint32_t ah[2][4], al[2][4], bh[4][4], bl[4][4];
            uint32_t koff = (uint32_t)(kk * 2) * 16;
            #pragma unroll
            for (int mi = 0; mi < 2; mi++) {
                uint32_t a = sa + (uint32_t)(wm + mi * 16) * ROWB + arow + koff;
                ldsm4(ah[mi], a + OFF_AH);
                ldsm4(al[mi], a + OFF_AL);
            }
            #pragma unroll
            for (int nb = 0; nb < 4; nb++) {
                uint32_t a = sa + (uint32_t)(wn + nb * 16) * ROWB + arow + koff;
                ldsm4(bh[nb], a + OFF_BH);
                ldsm4(bl[nb], a + OFF_BL);
            }
            // Term-major ordering: 16 independent MMAs per term; the revisit
            // distance on each accumulator is 16 MMAs, hiding HMMA latency.
            #pragma unroll
            for (int mi = 0; mi < 2; mi++)
                #pragma unroll
                for (int f = 0; f < 8; f++) {
                    int nb = f >> 1, p = f & 1;
                    mma16816(acc[mi][f], ah[mi], bh[nb][p], bh[nb][2 + p]);
                }
            #pragma unroll
            for (int mi = 0; mi < 2; mi++)
                #pragma unroll
                for (int f = 0; f < 8; f++) {
                    int nb = f >> 1, p = f & 1;
                    mma16816(acc[mi][f], al[mi], bh[nb][p], bh[nb][2 + p]);
                }
            #pragma unroll
            for (int mi = 0; mi < 2; mi++)
                #pragma unroll
                for (int f = 0; f < 8; f++) {
                    int nb = f >> 1, p = f & 1;
                    mma16816(acc[mi][f], ah[mi], bl[nb][p], bl[nb][2 + p]);
                }
        }
    }

    // ---- epilogue ----
    const int g = lane >> 2, t = lane & 3;
    #pragma unroll
    for (int mi = 0; mi < 2; mi++) {
        #pragma unroll
        for (int f = 0; f < 8; f++) {
            int row = bm + wm + mi * 16 + g;
            int col = bn + wn + f * 8 + t * 2;
            float b0 = __ldg(bias + col), b1 = __ldg(bias + col + 1);
            float v0 = acc[mi][f][0] + b0, v1 = acc[mi][f][1] + b1;
            float v2 = acc[mi][f][2] + b0, v3 = acc[mi][f][3] + b1;
            if (SPLIT_OUT) {
                v0 = fmaxf(v0, 0.f); v1 = fmaxf(v1, 0.f);
                v2 = fmaxf(v2, 0.f); v3 = fmaxf(v3, 0.f);
                __nv_bfloat16 h0, h1, h2, h3, l0, l1, l2, l3;
                split_bf16(v0, h0, l0); split_bf16(v1, h1, l1);
                split_bf16(v2, h2, l2); split_bf16(v3, h3, l3);
                uint32_t pa = ((uint32_t)__bfloat16_as_ushort(h1) << 16) | __bfloat16_as_ushort(h0);
                uint32_t pb = ((uint32_t)__bfloat16_as_ushort(h3) << 16) | __bfloat16_as_ushort(h2);
                uint32_t qa = ((uint32_t)__bfloat16_as_ushort(l1) << 16) | __bfloat16_as_ushort(l0);
                uint32_t qb = ((uint32_t)__bfloat16_as_ushort(l3) << 16) | __bfloat16_as_ushort(l2);
                *(uint32_t*)(Chi + (size_t)row * N + col) = pa;
                *(uint32_t*)(Chi + (size_t)(row + 8) * N + col) = pb;
                *(uint32_t*)(Clo + (size_t)row * N + col) = qa;
                *(uint32_t*)(Clo + (size_t)(row + 8) * N + col) = qb;
            } else {
                *(float2*)(Cf + (size_t)row * N + col) = make_float2(v0, v1);
                *(float2*)(Cf + (size_t)(row + 8) * N + col) = make_float2(v2, v3);
            }
        }
    }
}

extern "C" void kernel_launch(void* const* d_in, const int* in_sizes, int n_in,
                              void* d_out, int out_size) {
    const float* x  = (const float*)d_in[0];
    const float* w1 = (const float*)d_in[1];
    const float* b1 = (const float*)d_in[2];
    const float* w2 = (const float*)d_in[3];
    const float* b2 = (const float*)d_in[4];
    float* out = (float*)d_out;

    __nv_bfloat16 *xh, *xl, *hh, *hl, *w1th, *w1tl, *w2th, *w2tl;
    cudaGetSymbolAddress((void**)&xh, g_xh);
    cudaGetSymbolAddress((void**)&xl, g_xl);
    cudaGetSymbolAddress((void**)&hh, g_hh);
    cudaGetSymbolAddress((void**)&hl, g_hl);
    cudaGetSymbolAddress((void**)&w1th, g_w1th);
    cudaGetSymbolAddress((void**)&w1tl, g_w1tl);
    cudaGetSymbolAddress((void**)&w2th, g_w2th);
    cudaGetSymbolAddress((void**)&w2tl, g_w2tl);

    cudaFuncSetAttribute(ffn_mma<true>,  cudaFuncAttributeMaxDynamicSharedMemorySize, SMEM_DYN);
    cudaFuncSetAttribute(ffn_mma<false>, cudaFuncAttributeMaxDynamicSharedMemorySize, SMEM_DYN);

    {
        size_t n4 = (size_t)M_TOTAL * D_DIM / 4;
        split_kernel<<<(unsigned)((n4 + 255) / 256), 256>>>(x, xh, xl, n4);
    }
    transpose_split_kernel<<<dim3(W_DIM / 32, D_DIM / 32), dim3(32, 8)>>>(w1, w1th, w1tl, D_DIM, W_DIM);
    transpose_split_kernel<<<dim3(D_DIM / 32, W_DIM / 32), dim3(32, 8)>>>(w2, w2th, w2tl, W_DIM, D_DIM);

    ffn_mma<true><<<dim3(W_DIM / BNT, M_TOTAL / BMT), 256, SMEM_DYN>>>(
        xh, xl, w1th, w1tl, b1, nullptr, hh, hl, M_TOTAL, W_DIM, D_DIM);

    ffn_mma<false><<<dim3(D_DIM / BNT, M_TOTAL / BMT), 256, SMEM_DYN>>>(
        hh, hl, w2th, w2tl, b2, out, nullptr, nullptr, M_TOTAL, D_DIM, W_DIM);
}

// round 6
// speedup vs baseline: 1.5020x; 1.5020x over previous
#include <cuda_runtime.h>
#include <cuda_bf16.h>
#include <cstdint>
#include <cstddef>

// FFN: out = relu(x @ w1 + b1) @ w2 + b2
// bf16x3 split precision via mma.sync.m16n8k16.
// R6: 512 threads (16 warps, 4x4), warp tile 32x32 -> 4 warps/SMSP to feed tensor pipes.

#define M_TOTAL 8192
#define D_DIM   1024
#define W_DIM   4096

// ---- device scratch ----
__device__ __nv_bfloat16 g_xh[(size_t)M_TOTAL * D_DIM];
__device__ __nv_bfloat16 g_xl[(size_t)M_TOTAL * D_DIM];
__device__ __nv_bfloat16 g_hh[(size_t)M_TOTAL * W_DIM];
__device__ __nv_bfloat16 g_hl[(size_t)M_TOTAL * W_DIM];
__device__ __nv_bfloat16 g_w1th[(size_t)W_DIM * D_DIM];
__device__ __nv_bfloat16 g_w1tl[(size_t)W_DIM * D_DIM];
__device__ __nv_bfloat16 g_w2th[(size_t)D_DIM * W_DIM];
__device__ __nv_bfloat16 g_w2tl[(size_t)D_DIM * W_DIM];

// ---- helpers ----
__device__ __forceinline__ uint32_t smem_u32(const void* p) {
    uint32_t a;
    asm("{ .reg .u64 t; cvta.to.shared.u64 t, %1; cvt.u32.u64 %0, t; }" : "=r"(a) : "l"(p));
    return a;
}
__device__ __forceinline__ void cpasync16(uint32_t dst, const void* src) {
    asm volatile("cp.async.cg.shared.global [%0], [%1], 16;" :: "r"(dst), "l"(src));
}
__device__ __forceinline__ void cp_commit() {
    asm volatile("cp.async.commit_group;" ::: "memory");
}
__device__ __forceinline__ void cp_wait1() {
    asm volatile("cp.async.wait_group 1;" ::: "memory");
}
__device__ __forceinline__ void ldsm4(uint32_t* r, uint32_t addr) {
    asm volatile("ldmatrix.sync.aligned.m8n8.x4.shared.b16 {%0,%1,%2,%3}, [%4];"
                 : "=r"(r[0]), "=r"(r[1]), "=r"(r[2]), "=r"(r[3]) : "r"(addr));
}
__device__ __forceinline__ void mma16816(float* c, const uint32_t* a, uint32_t b0, uint32_t b1) {
    asm volatile("mma.sync.aligned.m16n8k16.row.col.f32.bf16.bf16.f32 "
                 "{%0,%1,%2,%3}, {%4,%5,%6,%7}, {%8,%9}, {%0,%1,%2,%3};"
                 : "+f"(c[0]), "+f"(c[1]), "+f"(c[2]), "+f"(c[3])
                 : "r"(a[0]), "r"(a[1]), "r"(a[2]), "r"(a[3]), "r"(b0), "r"(b1));
}
__device__ __forceinline__ void split_bf16(float v, __nv_bfloat16& hi, __nv_bfloat16& lo) {
    hi = __float2bfloat16_rn(v);
    lo = __float2bfloat16_rn(v - __bfloat162float(hi));
}

// ---- prepass: split fp32 -> bf16 hi/lo ----
__global__ void split_kernel(const float* __restrict__ X,
                             __nv_bfloat16* __restrict__ Xh,
                             __nv_bfloat16* __restrict__ Xl, size_t n4) {
    size_t i = (size_t)blockIdx.x * blockDim.x + threadIdx.x;
    if (i >= n4) return;
    float4 v = ((const float4*)X)[i];
    __nv_bfloat16 h0, h1, h2, h3, l0, l1, l2, l3;
    split_bf16(v.x, h0, l0); split_bf16(v.y, h1, l1);
    split_bf16(v.z, h2, l2); split_bf16(v.w, h3, l3);
    uint32_t ph0 = ((uint32_t)__bfloat16_as_ushort(h1) << 16) | __bfloat16_as_ushort(h0);
    uint32_t ph1 = ((uint32_t)__bfloat16_as_ushort(h3) << 16) | __bfloat16_as_ushort(h2);
    uint32_t pl0 = ((uint32_t)__bfloat16_as_ushort(l1) << 16) | __bfloat16_as_ushort(l0);
    uint32_t pl1 = ((uint32_t)__bfloat16_as_ushort(l3) << 16) | __bfloat16_as_ushort(l2);
    ((uint2*)Xh)[i] = make_uint2(ph0, ph1);
    ((uint2*)Xl)[i] = make_uint2(pl0, pl1);
}

// ---- prepass: W [K,N] fp32 -> W^T [N,K] bf16 hi/lo ----
__global__ void transpose_split_kernel(const float* __restrict__ W,
                                       __nv_bfloat16* __restrict__ Thi,
                                       __nv_bfloat16* __restrict__ Tlo,
                                       int K, int N) {
    __shared__ float t[32][33];
    int n0 = blockIdx.x * 32, k0 = blockIdx.y * 32;
    int tx = threadIdx.x, ty = threadIdx.y;
    #pragma unroll
    for (int j = 0; j < 4; j++)
        t[ty + 8 * j][tx] = W[(size_t)(k0 + ty + 8 * j) * N + n0 + tx];
    __syncthreads();
    #pragma unroll
    for (int j = 0; j < 4; j++) {
        float v = t[tx][ty + 8 * j];
        __nv_bfloat16 hi, lo;
        split_bf16(v, hi, lo);
        size_t o = (size_t)(n0 + ty + 8 * j) * K + k0 + tx;
        Thi[o] = hi;
        Tlo[o] = lo;
    }
}

// ---- main GEMM ----
// CTA tile 128x128x32, 512 threads (16 warps, 4x4), warp tile 32x32.
#define BMT 128
#define BNT 128
#define BKT 32
#define STAGES 3
#define ROWB 80                    // 32 bf16 = 64B + 16B pad
#define TILE_B (128 * ROWB)
#define STAGE_B (4 * TILE_B)
#define OFF_AH 0
#define OFF_AL TILE_B
#define OFF_BH (2 * TILE_B)
#define OFF_BL (3 * TILE_B)
#define SMEM_DYN (STAGES * STAGE_B)

template<bool SPLIT_OUT>
__global__ __launch_bounds__(512, 1)
void ffn_mma(const __nv_bfloat16* __restrict__ Ah, const __nv_bfloat16* __restrict__ Al,
             const __nv_bfloat16* __restrict__ Bh, const __nv_bfloat16* __restrict__ Bl,
             const float* __restrict__ bias,
             float* __restrict__ Cf,
             __nv_bfloat16* __restrict__ Chi, __nv_bfloat16* __restrict__ Clo,
             int M, int N, int K) {
    extern __shared__ char smem[];
    const uint32_t sbase = smem_u32(smem);
    const int tid = threadIdx.x;
    const int lane = tid & 31, wid = tid >> 5;
    const int wm = (wid >> 2) * 32, wn = (wid & 3) * 32;
    const int bm = blockIdx.y * BMT, bn = blockIdx.x * BNT;

    const __nv_bfloat16* Ahb = Ah + (size_t)bm * K;
    const __nv_bfloat16* Alb = Al + (size_t)bm * K;
    const __nv_bfloat16* Bhb = Bh + (size_t)bn * K;
    const __nv_bfloat16* Blb = Bl + (size_t)bn * K;

    const int ldr = tid >> 2;        // 0..127
    const int ldc = tid & 3;         // 16B chunk 0..3

    const int nIters = K / BKT;

    auto issue_stage = [&](int s) {
        uint32_t dst = sbase + (uint32_t)(s % STAGES) * STAGE_B;
        int k0 = s * BKT;
        uint32_t d = dst + (uint32_t)ldr * ROWB + (uint32_t)ldc * 16;
        size_t so = (size_t)ldr * K + k0 + ldc * 8;
        cpasync16(d + OFF_AH, Ahb + so);
        cpasync16(d + OFF_AL, Alb + so);
        cpasync16(d + OFF_BH, Bhb + so);
        cpasync16(d + OFF_BL, Blb + so);
        cp_commit();
    };

    issue_stage(0);
    issue_stage(1);

    float acc[2][4][4];
    #pragma unroll
    for (int mi = 0; mi < 2; mi++)
        #pragma unroll
        for (int f = 0; f < 4; f++)
            #pragma unroll
            for (int q = 0; q < 4; q++)
                acc[mi][f][q] = 0.0f;

    const uint32_t arow = (uint32_t)(lane & 15) * ROWB + (uint32_t)(lane >> 4) * 16;

    for (int i = 0; i < nIters; i++) {
        cp_wait1();
        __syncthreads();
        if (i + 2 < nIters) issue_stage(i + 2);
        else cp_commit();   // keep group accounting exact for wait_group 1

        uint32_t sa = sbase + (uint32_t)(i % STAGES) * STAGE_B;

        #pragma unroll
        for (int kk = 0; kk < 2; kk++) {
            uint32_t ah[2][4], al[2][4], bh[2][4], bl[2][4];
            uint32_t koff = (uint32_t)(kk * 2) * 16;
            #pragma unroll
            for (int mi = 0; mi < 2; mi++) {
                uint32_t a = sa + (uint32_t)(wm + mi * 16) * ROWB + arow + koff;
                ldsm4(ah[mi], a + OFF_AH);
                ldsm4(al[mi], a + OFF_AL);
            }
            #pragma unroll
            for (int nb = 0; nb < 2; nb++) {
                uint32_t a = sa + (uint32_t)(wn + nb * 16) * ROWB + arow + koff;
                ldsm4(bh[nb], a + OFF_BH);
                ldsm4(bl[nb], a + OFF_BL);
            }
            #pragma unroll
            for (int mi = 0; mi < 2; mi++)
                #pragma unroll
                for (int f = 0; f < 4; f++) {
                    int nb = f >> 1, p = f & 1;
                    mma16816(acc[mi][f], ah[mi], bh[nb][p], bh[nb][2 + p]);
                    mma16816(acc[mi][f], al[mi], bh[nb][p], bh[nb][2 + p]);
                    mma16816(acc[mi][f], ah[mi], bl[nb][p], bl[nb][2 + p]);
                }
        }
        __syncthreads();
    }

    // ---- epilogue ----
    const int g = lane >> 2, t = lane & 3;
    #pragma unroll
    for (int mi = 0; mi < 2; mi++) {
        #pragma unroll
        for (int f = 0; f < 4; f++) {
            int row = bm + wm + mi * 16 + g;
            int col = bn + wn + f * 8 + t * 2;
            float b0 = __ldg(bias + col), b1 = __ldg(bias + col + 1);
            float v0 = acc[mi][f][0] + b0, v1 = acc[mi][f][1] + b1;
            float v2 = acc[mi][f][2] + b0, v3 = acc[mi][f][3] + b1;
            if (SPLIT_OUT) {
                v0 = fmaxf(v0, 0.f); v1 = fmaxf(v1, 0.f);
                v2 = fmaxf(v2, 0.f); v3 = fmaxf(v3, 0.f);
                __nv_bfloat16 h0, h1, h2, h3, l0, l1, l2, l3;
                split_bf16(v0, h0, l0); split_bf16(v1, h1, l1);
                split_bf16(v2, h2, l2); split_bf16(v3, h3, l3);
                uint32_t pa = ((uint32_t)__bfloat16_as_ushort(h1) << 16) | __bfloat16_as_ushort(h0);
                uint32_t pb = ((uint32_t)__bfloat16_as_ushort(h3) << 16) | __bfloat16_as_ushort(h2);
                uint32_t qa = ((uint32_t)__bfloat16_as_ushort(l1) << 16) | __bfloat16_as_ushort(l0);
                uint32_t qb = ((uint32_t)__bfloat16_as_ushort(l3) << 16) | __bfloat16_as_ushort(l2);
                *(uint32_t*)(Chi + (size_t)row * N + col) = pa;
                *(uint32_t*)(Chi + (size_t)(row + 8) * N + col) = pb;
                *(uint32_t*)(Clo + (size_t)row * N + col) = qa;
                *(uint32_t*)(Clo + (size_t)(row + 8) * N + col) = qb;
            } else {
                *(float2*)(Cf + (size_t)row * N + col) = make_float2(v0, v1);
                *(float2*)(Cf + (size_t)(row + 8) * N + col) = make_float2(v2, v3);
            }
        }
    }
}

extern "C" void kernel_launch(void* const* d_in, const int* in_sizes, int n_in,
                              void* d_out, int out_size) {
    const float* x  = (const float*)d_in[0];
    const float* w1 = (const float*)d_in[1];
    const float* b1 = (const float*)d_in[2];
    const float* w2 = (const float*)d_in[3];
    const float* b2 = (const float*)d_in[4];
    float* out = (float*)d_out;

    __nv_bfloat16 *xh, *xl, *hh, *hl, *w1th, *w1tl, *w2th, *w2tl;
    cudaGetSymbolAddress((void**)&xh, g_xh);
    cudaGetSymbolAddress((void**)&xl, g_xl);
    cudaGetSymbolAddress((void**)&hh, g_hh);
    cudaGetSymbolAddress((void**)&hl, g_hl);
    cudaGetSymbolAddress((void**)&w1th, g_w1th);
    cudaGetSymbolAddress((void**)&w1tl, g_w1tl);
    cudaGetSymbolAddress((void**)&w2th, g_w2th);
    cudaGetSymbolAddress((void**)&w2tl, g_w2tl);

    cudaFuncSetAttribute(ffn_mma<true>,  cudaFuncAttributeMaxDynamicSharedMemorySize, SMEM_DYN);
    cudaFuncSetAttribute(ffn_mma<false>, cudaFuncAttributeMaxDynamicSharedMemorySize, SMEM_DYN);

    {
        size_t n4 = (size_t)M_TOTAL * D_DIM / 4;
        split_kernel<<<(unsigned)((n4 + 255) / 256), 256>>>(x, xh, xl, n4);
    }
    transpose_split_kernel<<<dim3(W_DIM / 32, D_DIM / 32), dim3(32, 8)>>>(w1, w1th, w1tl, D_DIM, W_DIM);
    transpose_split_kernel<<<dim3(D_DIM / 32, W_DIM / 32), dim3(32, 8)>>>(w2, w2th, w2tl, W_DIM, D_DIM);

    ffn_mma<true><<<dim3(W_DIM / BNT, M_TOTAL / BMT), 512, SMEM_DYN>>>(
        xh, xl, w1th, w1tl, b1, nullptr, hh, hl, M_TOTAL, W_DIM, D_DIM);

    ffn_mma<false><<<dim3(D_DIM / BNT, M_TOTAL / BMT), 512, SMEM_DYN>>>(
        hh, hl, w2th, w2tl, b2, out, nullptr, nullptr, M_TOTAL, D_DIM, W_DIM);
}

// round 7
// speedup vs baseline: 3.5110x; 2.3376x over previous
#include <cuda_runtime.h>
#include <cuda_fp16.h>
#include <cstdint>
#include <cstddef>

// FFN: out = relu(x @ w1 + b1) @ w2 + b2
// R7: single-term fp16 mma.sync.m16n8k16 (fp32 accum). HMMA.16816 issue rate
// (16 cyc/SMSP) is the proven ceiling -> 3x fewer MMAs than bf16x3 = 3x faster.

#define M_TOTAL 8192
#define D_DIM   1024
#define W_DIM   4096

// ---- device scratch ----
__device__ __half g_xh[(size_t)M_TOTAL * D_DIM];     // x as fp16
__device__ __half g_hh[(size_t)M_TOTAL * W_DIM];     // hidden as fp16
__device__ __half g_w1t[(size_t)W_DIM * D_DIM];      // w1^T fp16
__device__ __half g_w2t[(size_t)D_DIM * W_DIM];      // w2^T fp16

// ---- helpers ----
__device__ __forceinline__ uint32_t smem_u32(const void* p) {
    uint32_t a;
    asm("{ .reg .u64 t; cvta.to.shared.u64 t, %1; cvt.u32.u64 %0, t; }" : "=r"(a) : "l"(p));
    return a;
}
__device__ __forceinline__ void cpasync16(uint32_t dst, const void* src) {
    asm volatile("cp.async.cg.shared.global [%0], [%1], 16;" :: "r"(dst), "l"(src));
}
__device__ __forceinline__ void cp_commit() {
    asm volatile("cp.async.commit_group;" ::: "memory");
}
__device__ __forceinline__ void cp_wait1() {
    asm volatile("cp.async.wait_group 1;" ::: "memory");
}
__device__ __forceinline__ void ldsm4(uint32_t* r, uint32_t addr) {
    asm volatile("ldmatrix.sync.aligned.m8n8.x4.shared.b16 {%0,%1,%2,%3}, [%4];"
                 : "=r"(r[0]), "=r"(r[1]), "=r"(r[2]), "=r"(r[3]) : "r"(addr));
}
__device__ __forceinline__ void mma16816(float* c, const uint32_t* a, uint32_t b0, uint32_t b1) {
    asm volatile("mma.sync.aligned.m16n8k16.row.col.f32.f16.f16.f32 "
                 "{%0,%1,%2,%3}, {%4,%5,%6,%7}, {%8,%9}, {%0,%1,%2,%3};"
                 : "+f"(c[0]), "+f"(c[1]), "+f"(c[2]), "+f"(c[3])
                 : "r"(a[0]), "r"(a[1]), "r"(a[2]), "r"(a[3]), "r"(b0), "r"(b1));
}

// ---- prepass: fp32 -> fp16 ----
__global__ void cvt_half_kernel(const float* __restrict__ X,
                                __half* __restrict__ Xh, size_t n4) {
    size_t i = (size_t)blockIdx.x * blockDim.x + threadIdx.x;
    if (i >= n4) return;
    float4 v = ((const float4*)X)[i];
    uint32_t p0 = ((uint32_t)__half_as_ushort(__float2half_rn(v.y)) << 16)
                 | __half_as_ushort(__float2half_rn(v.x));
    uint32_t p1 = ((uint32_t)__half_as_ushort(__float2half_rn(v.w)) << 16)
                 | __half_as_ushort(__float2half_rn(v.z));
    ((uint2*)Xh)[i] = make_uint2(p0, p1);
}

// ---- prepass: W [K,N] fp32 -> W^T [N,K] fp16 ----
__global__ void transpose_half_kernel(const float* __restrict__ W,
                                      __half* __restrict__ T,
                                      int K, int N) {
    __shared__ float t[32][33];
    int n0 = blockIdx.x * 32, k0 = blockIdx.y * 32;
    int tx = threadIdx.x, ty = threadIdx.y;
    #pragma unroll
    for (int j = 0; j < 4; j++)
        t[ty + 8 * j][tx] = W[(size_t)(k0 + ty + 8 * j) * N + n0 + tx];
    __syncthreads();
    #pragma unroll
    for (int j = 0; j < 4; j++) {
        float v = t[tx][ty + 8 * j];
        T[(size_t)(n0 + ty + 8 * j) * K + k0 + tx] = __float2half_rn(v);
    }
}

// ---- main GEMM ----
// CTA tile 128x128x32, 512 threads (16 warps, 4x4), warp tile 32x32, 3-stage cp.async.
#define BMT 128
#define BNT 128
#define BKT 32
#define STAGES 3
#define ROWB 80                    // 32 fp16 = 64B + 16B pad
#define TILE_B (128 * ROWB)
#define STAGE_B (2 * TILE_B)       // A tile + B tile
#define OFF_A 0
#define OFF_B TILE_B
#define SMEM_DYN (STAGES * STAGE_B)

template<bool RELU_H16>   // true: write relu(.) as fp16 to Ch; false: fp32 to Cf
__global__ __launch_bounds__(512, 1)
void ffn_mma(const __half* __restrict__ A,
             const __half* __restrict__ B,
             const float* __restrict__ bias,
             float* __restrict__ Cf,
             __half* __restrict__ Ch,
             int M, int N, int K) {
    extern __shared__ char smem[];
    const uint32_t sbase = smem_u32(smem);
    const int tid = threadIdx.x;
    const int lane = tid & 31, wid = tid >> 5;
    const int wm = (wid >> 2) * 32, wn = (wid & 3) * 32;
    const int bm = blockIdx.y * BMT, bn = blockIdx.x * BNT;

    const __half* Ab = A + (size_t)bm * K;
    const __half* Bb = B + (size_t)bn * K;

    const int ldr = tid >> 2;        // 0..127
    const int ldc = tid & 3;         // 16B chunk 0..3

    const int nIters = K / BKT;

    auto issue_stage = [&](int s) {
        uint32_t dst = sbase + (uint32_t)(s % STAGES) * STAGE_B;
        int k0 = s * BKT;
        uint32_t d = dst + (uint32_t)ldr * ROWB + (uint32_t)ldc * 16;
        size_t so = (size_t)ldr * K + k0 + ldc * 8;
        cpasync16(d + OFF_A, Ab + so);
        cpasync16(d + OFF_B, Bb + so);
        cp_commit();
    };

    issue_stage(0);
    issue_stage(1);

    float acc[2][4][4];
    #pragma unroll
    for (int mi = 0; mi < 2; mi++)
        #pragma unroll
        for (int f = 0; f < 4; f++)
            #pragma unroll
            for (int q = 0; q < 4; q++)
                acc[mi][f][q] = 0.0f;

    const uint32_t arow = (uint32_t)(lane & 15) * ROWB + (uint32_t)(lane >> 4) * 16;

    for (int i = 0; i < nIters; i++) {
        cp_wait1();
        __syncthreads();
        if (i + 2 < nIters) issue_stage(i + 2);
        else cp_commit();   // keep group accounting exact for wait_group 1

        uint32_t sa = sbase + (uint32_t)(i % STAGES) * STAGE_B;

        #pragma unroll
        for (int kk = 0; kk < 2; kk++) {
            uint32_t ah[2][4], bh[2][4];
            uint32_t koff = (uint32_t)(kk * 2) * 16;
            #pragma unroll
            for (int mi = 0; mi < 2; mi++) {
                uint32_t a = sa + (uint32_t)(wm + mi * 16) * ROWB + arow + koff;
                ldsm4(ah[mi], a + OFF_A);
            }
            #pragma unroll
            for (int nb = 0; nb < 2; nb++) {
                uint32_t a = sa + (uint32_t)(wn + nb * 16) * ROWB + arow + koff;
                ldsm4(bh[nb], a + OFF_B);
            }
            #pragma unroll
            for (int mi = 0; mi < 2; mi++)
                #pragma unroll
                for (int f = 0; f < 4; f++) {
                    int nb = f >> 1, p = f & 1;
                    mma16816(acc[mi][f], ah[mi], bh[nb][p], bh[nb][2 + p]);
                }
        }
        __syncthreads();
    }

    // ---- epilogue ----
    const int g = lane >> 2, t = lane & 3;
    #pragma unroll
    for (int mi = 0; mi < 2; mi++) {
        #pragma unroll
        for (int f = 0; f < 4; f++) {
            int row = bm + wm + mi * 16 + g;
            int col = bn + wn + f * 8 + t * 2;
            float b0 = __ldg(bias + col), b1 = __ldg(bias + col + 1);
            float v0 = acc[mi][f][0] + b0, v1 = acc[mi][f][1] + b1;
            float v2 = acc[mi][f][2] + b0, v3 = acc[mi][f][3] + b1;
            if (RELU_H16) {
                v0 = fmaxf(v0, 0.f); v1 = fmaxf(v1, 0.f);
                v2 = fmaxf(v2, 0.f); v3 = fmaxf(v3, 0.f);
                uint32_t pa = ((uint32_t)__half_as_ushort(__float2half_rn(v1)) << 16)
                             | __half_as_ushort(__float2half_rn(v0));
                uint32_t pb = ((uint32_t)__half_as_ushort(__float2half_rn(v3)) << 16)
                             | __half_as_ushort(__float2half_rn(v2));
                *(uint32_t*)(Ch + (size_t)row * N + col) = pa;
                *(uint32_t*)(Ch + (size_t)(row + 8) * N + col) = pb;
            } else {
                *(float2*)(Cf + (size_t)row * N + col) = make_float2(v0, v1);
                *(float2*)(Cf + (size_t)(row + 8) * N + col) = make_float2(v2, v3);
            }
        }
    }
}

extern "C" void kernel_launch(void* const* d_in, const int* in_sizes, int n_in,
                              void* d_out, int out_size) {
    const float* x  = (const float*)d_in[0];
    const float* w1 = (const float*)d_in[1];
    const float* b1 = (const float*)d_in[2];
    const float* w2 = (const float*)d_in[3];
    const float* b2 = (const float*)d_in[4];
    float* out = (float*)d_out;

    __half *xh, *hh, *w1t, *w2t;
    cudaGetSymbolAddress((void**)&xh, g_xh);
    cudaGetSymbolAddress((void**)&hh, g_hh);
    cudaGetSymbolAddress((void**)&w1t, g_w1t);
    cudaGetSymbolAddress((void**)&w2t, g_w2t);

    cudaFuncSetAttribute(ffn_mma<true>,  cudaFuncAttributeMaxDynamicSharedMemorySize, SMEM_DYN);
    cudaFuncSetAttribute(ffn_mma<false>, cudaFuncAttributeMaxDynamicSharedMemorySize, SMEM_DYN);

    {
        size_t n4 = (size_t)M_TOTAL * D_DIM / 4;
        cvt_half_kernel<<<(unsigned)((n4 + 255) / 256), 256>>>(x, xh, n4);
    }
    transpose_half_kernel<<<dim3(W_DIM / 32, D_DIM / 32), dim3(32, 8)>>>(w1, w1t, D_DIM, W_DIM);
    transpose_half_kernel<<<dim3(D_DIM / 32, W_DIM / 32), dim3(32, 8)>>>(w2, w2t, W_DIM, D_DIM);

    // GEMM1: h = relu(x @ w1 + b1) -> fp16
    ffn_mma<true><<<dim3(W_DIM / BNT, M_TOTAL / BMT), 512, SMEM_DYN>>>(
        xh, w1t, b1, nullptr, hh, M_TOTAL, W_DIM, D_DIM);

    // GEMM2: out = h @ w2 + b2 -> fp32
    ffn_mma<false><<<dim3(D_DIM / BNT, M_TOTAL / BMT), 512, SMEM_DYN>>>(
        hh, w2t, b2, out, nullptr, M_TOTAL, D_DIM, W_DIM);
}

// round 8
// speedup vs baseline: 4.2660x; 1.2150x over previous
#include <cuda_runtime.h>
#include <cuda_fp16.h>
#include <cstdint>
#include <cstddef>

// FFN: out = relu(x @ w1 + b1) @ w2 + b2
// R8: single-term fp16 mma.sync; 256 thr/CTA (8 warps, warp tile 32x64),
// 3-stage cp.async, 60KB smem/CTA -> 2 CTAs/SM to overlap barrier/load overhead
// with the other CTA's HMMA issue.

#define M_TOTAL 8192
#define D_DIM   1024
#define W_DIM   4096

// ---- device scratch ----
__device__ __half g_xh[(size_t)M_TOTAL * D_DIM];
__device__ __half g_hh[(size_t)M_TOTAL * W_DIM];
__device__ __half g_w1t[(size_t)W_DIM * D_DIM];
__device__ __half g_w2t[(size_t)D_DIM * W_DIM];

// ---- helpers ----
__device__ __forceinline__ uint32_t smem_u32(const void* p) {
    uint32_t a;
    asm("{ .reg .u64 t; cvta.to.shared.u64 t, %1; cvt.u32.u64 %0, t; }" : "=r"(a) : "l"(p));
    return a;
}
__device__ __forceinline__ void cpasync16(uint32_t dst, const void* src) {
    asm volatile("cp.async.cg.shared.global [%0], [%1], 16;" :: "r"(dst), "l"(src));
}
__device__ __forceinline__ void cp_commit() {
    asm volatile("cp.async.commit_group;" ::: "memory");
}
__device__ __forceinline__ void cp_wait1() {
    asm volatile("cp.async.wait_group 1;" ::: "memory");
}
__device__ __forceinline__ void ldsm4(uint32_t* r, uint32_t addr) {
    asm volatile("ldmatrix.sync.aligned.m8n8.x4.shared.b16 {%0,%1,%2,%3}, [%4];"
                 : "=r"(r[0]), "=r"(r[1]), "=r"(r[2]), "=r"(r[3]) : "r"(addr));
}
__device__ __forceinline__ void mma16816(float* c, const uint32_t* a, uint32_t b0, uint32_t b1) {
    asm volatile("mma.sync.aligned.m16n8k16.row.col.f32.f16.f16.f32 "
                 "{%0,%1,%2,%3}, {%4,%5,%6,%7}, {%8,%9}, {%0,%1,%2,%3};"
                 : "+f"(c[0]), "+f"(c[1]), "+f"(c[2]), "+f"(c[3])
                 : "r"(a[0]), "r"(a[1]), "r"(a[2]), "r"(a[3]), "r"(b0), "r"(b1));
}

// ---- prepass: fp32 -> fp16 ----
__global__ void cvt_half_kernel(const float* __restrict__ X,
                                __half* __restrict__ Xh, size_t n4) {
    size_t i = (size_t)blockIdx.x * blockDim.x + threadIdx.x;
    if (i >= n4) return;
    float4 v = ((const float4*)X)[i];
    uint32_t p0 = ((uint32_t)__half_as_ushort(__float2half_rn(v.y)) << 16)
                 | __half_as_ushort(__float2half_rn(v.x));
    uint32_t p1 = ((uint32_t)__half_as_ushort(__float2half_rn(v.w)) << 16)
                 | __half_as_ushort(__float2half_rn(v.z));
    ((uint2*)Xh)[i] = make_uint2(p0, p1);
}

// ---- prepass: W [K,N] fp32 -> W^T [N,K] fp16 ----
__global__ void transpose_half_kernel(const float* __restrict__ W,
                                      __half* __restrict__ T,
                                      int K, int N) {
    __shared__ float t[32][33];
    int n0 = blockIdx.x * 32, k0 = blockIdx.y * 32;
    int tx = threadIdx.x, ty = threadIdx.y;
    #pragma unroll
    for (int j = 0; j < 4; j++)
        t[ty + 8 * j][tx] = W[(size_t)(k0 + ty + 8 * j) * N + n0 + tx];
    __syncthreads();
    #pragma unroll
    for (int j = 0; j < 4; j++) {
        float v = t[tx][ty + 8 * j];
        T[(size_t)(n0 + ty + 8 * j) * K + k0 + tx] = __float2half_rn(v);
    }
}

// ---- main GEMM ----
// CTA tile 128x128x32, 256 threads (8 warps, 4x2), warp tile 32x64, 3 stages.
#define BMT 128
#define BNT 128
#define BKT 32
#define STAGES 3
#define ROWB 80                    // 32 fp16 = 64B + 16B pad
#define TILE_B (128 * ROWB)        // 10240
#define STAGE_B (2 * TILE_B)       // 20480
#define OFF_A 0
#define OFF_B TILE_B
#define SMEM_DYN (STAGES * STAGE_B)   // 61440 -> 2 CTAs/SM

template<bool RELU_H16>
__global__ __launch_bounds__(256, 2)
void ffn_mma(const __half* __restrict__ A,
             const __half* __restrict__ B,
             const float* __restrict__ bias,
             float* __restrict__ Cf,
             __half* __restrict__ Ch,
             int M, int N, int K) {
    extern __shared__ char smem[];
    const uint32_t sbase = smem_u32(smem);
    const int tid = threadIdx.x;
    const int lane = tid & 31, wid = tid >> 5;
    const int wm = (wid >> 1) * 32, wn = (wid & 1) * 64;
    const int bm = blockIdx.y * BMT, bn = blockIdx.x * BNT;

    const __half* Ab = A + (size_t)bm * K;
    const __half* Bb = B + (size_t)bn * K;

    const int ldr = tid >> 2;        // 0..63
    const int ldc = tid & 3;         // 16B chunk 0..3

    const int nIters = K / BKT;

    auto issue_stage = [&](int s) {
        uint32_t dst = sbase + (uint32_t)(s % STAGES) * STAGE_B;
        int k0 = s * BKT;
        #pragma unroll
        for (int h = 0; h < 2; h++) {
            int row = ldr + h * 64;
            uint32_t d = dst + (uint32_t)row * ROWB + (uint32_t)ldc * 16;
            size_t so = (size_t)row * K + k0 + ldc * 8;
            cpasync16(d + OFF_A, Ab + so);
            cpasync16(d + OFF_B, Bb + so);
        }
        cp_commit();
    };

    issue_stage(0);
    issue_stage(1);

    float acc[2][8][4];
    #pragma unroll
    for (int mi = 0; mi < 2; mi++)
        #pragma unroll
        for (int f = 0; f < 8; f++)
            #pragma unroll
            for (int q = 0; q < 4; q++)
                acc[mi][f][q] = 0.0f;

    const uint32_t arow = (uint32_t)(lane & 15) * ROWB + (uint32_t)(lane >> 4) * 16;

    for (int i = 0; i < nIters; i++) {
        cp_wait1();
        __syncthreads();
        if (i + 2 < nIters) issue_stage(i + 2);
        else cp_commit();   // keep group accounting exact for wait_group 1

        uint32_t sa = sbase + (uint32_t)(i % STAGES) * STAGE_B;

        #pragma unroll
        for (int kk = 0; kk < 2; kk++) {
            uint32_t ah[2][4], bh[4][4];
            uint32_t koff = (uint32_t)(kk * 2) * 16;
            #pragma unroll
            for (int mi = 0; mi < 2; mi++) {
                uint32_t a = sa + (uint32_t)(wm + mi * 16) * ROWB + arow + koff;
                ldsm4(ah[mi], a + OFF_A);
            }
            #pragma unroll
            for (int nb = 0; nb < 4; nb++) {
                uint32_t a = sa + (uint32_t)(wn + nb * 16) * ROWB + arow + koff;
                ldsm4(bh[nb], a + OFF_B);
            }
            #pragma unroll
            for (int mi = 0; mi < 2; mi++)
                #pragma unroll
                for (int f = 0; f < 8; f++) {
                    int nb = f >> 1, p = f & 1;
                    mma16816(acc[mi][f], ah[mi], bh[nb][p], bh[nb][2 + p]);
                }
        }
        __syncthreads();
    }

    // ---- epilogue ----
    const int g = lane >> 2, t = lane & 3;
    #pragma unroll
    for (int mi = 0; mi < 2; mi++) {
        #pragma unroll
        for (int f = 0; f < 8; f++) {
            int row = bm + wm + mi * 16 + g;
            int col = bn + wn + f * 8 + t * 2;
            float b0 = __ldg(bias + col), b1 = __ldg(bias + col + 1);
            float v0 = acc[mi][f][0] + b0, v1 = acc[mi][f][1] + b1;
            float v2 = acc[mi][f][2] + b0, v3 = acc[mi][f][3] + b1;
            if (RELU_H16) {
                v0 = fmaxf(v0, 0.f); v1 = fmaxf(v1, 0.f);
                v2 = fmaxf(v2, 0.f); v3 = fmaxf(v3, 0.f);
                uint32_t pa = ((uint32_t)__half_as_ushort(__float2half_rn(v1)) << 16)
                             | __half_as_ushort(__float2half_rn(v0));
                uint32_t pb = ((uint32_t)__half_as_ushort(__float2half_rn(v3)) << 16)
                             | __half_as_ushort(__float2half_rn(v2));
                *(uint32_t*)(Ch + (size_t)row * N + col) = pa;
                *(uint32_t*)(Ch + (size_t)(row + 8) * N + col) = pb;
            } else {
                *(float2*)(Cf + (size_t)row * N + col) = make_float2(v0, v1);
                *(float2*)(Cf + (size_t)(row + 8) * N + col) = make_float2(v2, v3);
            }
        }
    }
}

extern "C" void kernel_launch(void* const* d_in, const int* in_sizes, int n_in,
                              void* d_out, int out_size) {
    const float* x  = (const float*)d_in[0];
    const float* w1 = (const float*)d_in[1];
    const float* b1 = (const float*)d_in[2];
    const float* w2 = (const float*)d_in[3];
    const float* b2 = (const float*)d_in[4];
    float* out = (float*)d_out;

    __half *xh, *hh, *w1t, *w2t;
    cudaGetSymbolAddress((void**)&xh, g_xh);
    cudaGetSymbolAddress((void**)&hh, g_hh);
    cudaGetSymbolAddress((void**)&w1t, g_w1t);
    cudaGetSymbolAddress((void**)&w2t, g_w2t);

    cudaFuncSetAttribute(ffn_mma<true>,  cudaFuncAttributeMaxDynamicSharedMemorySize, SMEM_DYN);
    cudaFuncSetAttribute(ffn_mma<false>, cudaFuncAttributeMaxDynamicSharedMemorySize, SMEM_DYN);

    {
        size_t n4 = (size_t)M_TOTAL * D_DIM / 4;
        cvt_half_kernel<<<(unsigned)((n4 + 255) / 256), 256>>>(x, xh, n4);
    }
    transpose_half_kernel<<<dim3(W_DIM / 32, D_DIM / 32), dim3(32, 8)>>>(w1, w1t, D_DIM, W_DIM);
    transpose_half_kernel<<<dim3(D_DIM / 32, W_DIM / 32), dim3(32, 8)>>>(w2, w2t, W_DIM, D_DIM);

    // GEMM1: h = relu(x @ w1 + b1) -> fp16
    ffn_mma<true><<<dim3(W_DIM / BNT, M_TOTAL / BMT), 256, SMEM_DYN>>>(
        xh, w1t, b1, nullptr, hh, M_TOTAL, W_DIM, D_DIM);

    // GEMM2: out = h @ w2 + b2 -> fp32
    ffn_mma<false><<<dim3(D_DIM / BNT, M_TOTAL / BMT), 256, SMEM_DYN>>>(
        hh, w2t, b2, out, nullptr, M_TOTAL, D_DIM, W_DIM);
}